// round 9
// baseline (speedup 1.0000x reference)
#include <cuda_runtime.h>
#include <cuda_bf16.h>
#include <cstdint>

// Problem constants (match reference)
#define NUM_TABLES 26
#define NUM_EMB    100000
#define EMB_DIM    64
#define DENSE_DIM  512
#define BATCH      4096
#define BAG        50
#define HIDDEN_OUT 512
#define FEAT_DIM   (NUM_TABLES * EMB_DIM + EMB_DIM)   // 1728

typedef unsigned long long u64;

// Scratch (device globals — no allocation allowed)
__device__ __align__(256) float g_H1[BATCH * DENSE_DIM];     // dense hidden
__device__ __align__(256) float g_FEAT[BATCH * FEAT_DIM];    // concat features
__device__ __align__(256) float g_H2[BATCH * HIDDEN_OUT];    // output hidden
__device__ int g_idx_is64;                                   // index dtype flag

// ---------------------------------------------------------------------------
// Packed helpers: FFMA2 (double-rate fp32) + register-side operand packing.
// ---------------------------------------------------------------------------
__device__ __forceinline__ void ffma2(u64& d, u64 a, u64 b)
{
    asm("fma.rn.f32x2 %0, %1, %2, %0;" : "+l"(d) : "l"(a), "l"(b));
}
__device__ __forceinline__ u64 dup2(float a)   // (a,a) packed — 1 ALU op
{
    u64 r;
    asm("mov.b64 %0, {%1, %1};" : "=l"(r) : "r"(__float_as_uint(a)));
    return r;
}
__device__ __forceinline__ float2 u2f2(u64 u)
{
    float2 f;
    asm("mov.b64 {%0, %1}, %2;" : "=f"(f.x), "=f"(f.y) : "l"(u));
    return f;
}

// ---------------------------------------------------------------------------
// Index dtype detection (int64 LE buffer has all-zero odd words).
// ---------------------------------------------------------------------------
__global__ void detect_idx_dtype_kernel(const int* __restrict__ idx)
{
    int o = 0;
    #pragma unroll 8
    for (int i = 1; i < 512; i += 2) o |= idx[i];
    g_idx_is64 = (o == 0) ? 1 : 0;
}

// ---------------------------------------------------------------------------
// GEMM tile body, FFMA2 mainloop.
// C[m,n] = relu( sum_k A[m,k]*B[n,k] + bias[n] ); A [M,K] rm, B [N,K] rm.
// B pairs read directly as ulonglong2 from k-major smem (adjacent columns);
// A duplicated in REGISTERS (mov.b64), not in smem (R6's mistake).
// Requires TM%4==0, TN%4==0, BK%4==0, exact tiling.
// ---------------------------------------------------------------------------
template<int BM, int BN, int BK, int TM, int TN, int THREADS>
__device__ __forceinline__
void gemm_body(const float* __restrict__ A,
               const float* __restrict__ B,
               const float* __restrict__ bias,
               float* __restrict__ C,
               int K, int ldc, int bm0, int bn0,
               float* __restrict__ As_,   // [BK][BM]
               float* __restrict__ Bs_)   // [BK][BN]
{
    const int tid = threadIdx.x;
    const int tx  = tid % (BN/TN);
    const int ty  = tid / (BN/TN);

    float (*As)[BM] = (float(*)[BM])As_;
    float (*Bs)[BN] = (float(*)[BN])Bs_;

    u64 acc[TM][TN/2];
    #pragma unroll
    for (int i = 0; i < TM; i++)
        #pragma unroll
        for (int j = 0; j < TN/2; j++) acc[i][j] = 0ull;

    for (int k0 = 0; k0 < K; k0 += BK) {
        #pragma unroll
        for (int i = tid; i < BM*BK/4; i += THREADS) {
            int row = (i*4) / BK;
            int kk  = (i*4) % BK;
            float4 v = *(const float4*)(A + (size_t)(bm0 + row) * K + k0 + kk);
            As[kk+0][row] = v.x; As[kk+1][row] = v.y;
            As[kk+2][row] = v.z; As[kk+3][row] = v.w;
        }
        #pragma unroll
        for (int i = tid; i < BN*BK/4; i += THREADS) {
            int row = (i*4) / BK;
            int kk  = (i*4) % BK;
            float4 v = *(const float4*)(B + (size_t)(bn0 + row) * K + k0 + kk);
            Bs[kk+0][row] = v.x; Bs[kk+1][row] = v.y;
            Bs[kk+2][row] = v.z; Bs[kk+3][row] = v.w;
        }
        __syncthreads();

        #pragma unroll
        for (int k = 0; k < BK; k++) {
            // A fragment: float4 loads, duplicate each into a 64-bit (a,a)
            u64 a2[TM];
            #pragma unroll
            for (int i = 0; i < TM; i += 4) {
                float4 v = *(const float4*)&As[k][ty*TM + i];
                a2[i+0] = dup2(v.x); a2[i+1] = dup2(v.y);
                a2[i+2] = dup2(v.z); a2[i+3] = dup2(v.w);
            }
            // B fragment: pairs are naturally adjacent -> direct 64-bit reads
            u64 b2[TN/2];
            #pragma unroll
            for (int j = 0; j < TN; j += 4) {
                ulonglong2 v = *(const ulonglong2*)&Bs[k][tx*TN + j];
                b2[j/2]   = v.x;
                b2[j/2+1] = v.y;
            }
            #pragma unroll
            for (int i = 0; i < TM; i++)
                #pragma unroll
                for (int j = 0; j < TN/2; j++)
                    ffma2(acc[i][j], a2[i], b2[j]);
        }
        __syncthreads();
    }

    // Epilogue: bias + relu, float4 stores
    #pragma unroll
    for (int i = 0; i < TM; i++) {
        int row = bm0 + ty*TM + i;
        #pragma unroll
        for (int j = 0; j < TN; j += 4) {
            int col = bn0 + tx*TN + j;
            float2 f0 = u2f2(acc[i][j/2]);
            float2 f1 = u2f2(acc[i][j/2+1]);
            float4 o;
            o.x = fmaxf(f0.x + bias[col+0], 0.f);
            o.y = fmaxf(f0.y + bias[col+1], 0.f);
            o.z = fmaxf(f1.x + bias[col+2], 0.f);
            o.w = fmaxf(f1.y + bias[col+3], 0.f);
            *(float4*)(C + (size_t)row * ldc + col) = o;
        }
    }
}

// ---------------------------------------------------------------------------
// Pool body: one warp per (table, batch) bag. Runtime int32/int64, clamped
// indices, chunks of 10 for gather MLP, table-major order for L2 reuse.
// ---------------------------------------------------------------------------
__device__ __forceinline__
void pool_body(int bag, const int* __restrict__ idx,
               const float* __restrict__ tables, float* __restrict__ feat)
{
    if (bag >= NUM_TABLES * BATCH) return;
    const int t    = bag / BATCH;
    const int b    = bag % BATCH;
    const int lane = threadIdx.x & 31;
    const int is64 = g_idx_is64;

    const size_t bag_off = ((size_t)t * BATCH + b) * BAG;
    const float* tbl = tables + (size_t)t * NUM_EMB * EMB_DIM;

    float2 acc = make_float2(0.f, 0.f);
    #pragma unroll
    for (int l0 = 0; l0 < BAG; l0 += 10) {
        int ids[10];
        if (is64) {
            const long long* ip = (const long long*)idx + bag_off + l0;
            #pragma unroll
            for (int j = 0; j < 10; j++) ids[j] = (int)__ldg(&ip[j]);
        } else {
            const int* ip = idx + bag_off + l0;
            #pragma unroll
            for (int j = 0; j < 10; j++) ids[j] = __ldg(&ip[j]);
        }
        #pragma unroll
        for (int j = 0; j < 10; j++) {
            int id = min(max(ids[j], 0), NUM_EMB - 1);
            const float2* row = (const float2*)(tbl + (size_t)id * EMB_DIM);
            float2 v = __ldg(&row[lane]);
            acc.x += v.x; acc.y += v.y;
        }
    }
    float* out = feat + (size_t)b * FEAT_DIM + EMB_DIM + (size_t)t * EMB_DIM;
    ((float2*)out)[lane] = acc;
}

// ---------------------------------------------------------------------------
// Stage 1 fused (128-thread blocks): blocks [0, 256) run gemm1 tiles
// (128x64, TM=TN=8), the rest run pooling (4 warps/block).
// ---------------------------------------------------------------------------
#define G1_BM 128
#define G1_BN 64
#define G1_NB (DENSE_DIM / G1_BN)                     // 8
#define G1_MB (BATCH / G1_BM)                         // 32
#define G1_BLOCKS (G1_NB * G1_MB)                     // 256
#define POOL_WPB 4
#define POOL_BLOCKS ((NUM_TABLES * BATCH) / POOL_WPB) // 26624

__global__ __launch_bounds__(128)
void fused_stage1_kernel(const float* __restrict__ dense,
                         const float* __restrict__ w1,
                         const float* __restrict__ b1,
                         float* __restrict__ H1,
                         const int* __restrict__ sidx,
                         const float* __restrict__ emb,
                         float* __restrict__ feat)
{
    __shared__ __align__(16) float smem[16 * G1_BM + 16 * G1_BN];  // 12 KB
    if (blockIdx.x < G1_BLOCKS) {
        int bn = blockIdx.x % G1_NB;
        int bm = blockIdx.x / G1_NB;
        gemm_body<G1_BM, G1_BN, 16, 8, 8, 128>(dense, w1, b1, H1,
                                               DENSE_DIM, DENSE_DIM,
                                               bm * G1_BM, bn * G1_BN,
                                               smem, smem + 16 * G1_BM);
    } else {
        int bag = (blockIdx.x - G1_BLOCKS) * POOL_WPB + (threadIdx.x >> 5);
        pool_body(bag, sidx, emb, feat);
    }
}

// ---------------------------------------------------------------------------
// Standalone GEMM wrapper
// ---------------------------------------------------------------------------
template<int BM, int BN, int BK, int TM, int TN>
__global__ __launch_bounds__((BM/TM)*(BN/TN))
void gemm_kernel(const float* __restrict__ A, const float* __restrict__ B,
                 const float* __restrict__ bias, float* __restrict__ C,
                 int K, int ldc)
{
    constexpr int THREADS = (BM/TM)*(BN/TN);
    __shared__ __align__(16) float smem[BK*BM + BK*BN];
    gemm_body<BM, BN, BK, TM, TN, THREADS>(A, B, bias, C, K, ldc,
                                           blockIdx.y * BM, blockIdx.x * BN,
                                           smem, smem + BK * BM);
}

// ---------------------------------------------------------------------------
// Final layer: logits[b] = relu( dot(H2[b,:], w2[:]) + b2 ). One warp per row.
// ---------------------------------------------------------------------------
__global__ __launch_bounds__(256)
void out_final_kernel(const float* __restrict__ H2,
                      const float* __restrict__ w2,
                      const float* __restrict__ b2,
                      float* __restrict__ out)
{
    const int warp = (blockIdx.x * blockDim.x + threadIdx.x) >> 5;
    const int lane = threadIdx.x & 31;
    if (warp >= BATCH) return;

    const float4* h4 = (const float4*)(H2 + (size_t)warp * HIDDEN_OUT);
    const float4* w4 = (const float4*)w2;
    float s = 0.f;
    #pragma unroll
    for (int i = 0; i < HIDDEN_OUT/4/32; i++) {
        float4 h = h4[lane + i*32];
        float4 w = __ldg(&w4[lane + i*32]);
        s = fmaf(h.x, w.x, s); s = fmaf(h.y, w.y, s);
        s = fmaf(h.z, w.z, s); s = fmaf(h.w, w.w, s);
    }
    #pragma unroll
    for (int o = 16; o; o >>= 1) s += __shfl_xor_sync(0xFFFFFFFFu, s, o);
    if (lane == 0) out[warp] = fmaxf(s + b2[0], 0.f);
}

// ---------------------------------------------------------------------------
// Launch. Single stream; overlap inside fused_stage1.
// ---------------------------------------------------------------------------
extern "C" void kernel_launch(void* const* d_in, const int* in_sizes, int n_in,
                              void* d_out, int out_size)
{
    const float* dense = (const float*)d_in[0];       // [4096, 512]
    const int*   sidx  = (const int*)d_in[1];         // [26, 4096, 50]
    const float* emb   = (const float*)d_in[2];       // [26, 100000, 64]
    const float* d_w1  = (const float*)d_in[3];       // [512, 512]
    const float* d_b1  = (const float*)d_in[4];       // [512]
    const float* d_w2  = (const float*)d_in[5];       // [64, 512]
    const float* d_b2  = (const float*)d_in[6];       // [64]
    const float* o_w1  = (const float*)d_in[7];       // [512, 1728]
    const float* o_b1  = (const float*)d_in[8];       // [512]
    const float* o_w2  = (const float*)d_in[9];       // [1, 512]
    const float* o_b2  = (const float*)d_in[10];      // [1]
    float* out = (float*)d_out;                       // [4096, 1]

    static float* H1   = nullptr;
    static float* FEAT = nullptr;
    static float* H2   = nullptr;
    if (!H1) {
        cudaGetSymbolAddress((void**)&H1,   g_H1);
        cudaGetSymbolAddress((void**)&FEAT, g_FEAT);
        cudaGetSymbolAddress((void**)&H2,   g_H2);
    }

    // 0) index dtype detection
    detect_idx_dtype_kernel<<<1, 1>>>(sidx);

    // 1) fused: gemm1 (dense MLP layer 1 -> H1) + embedding pooling -> FEAT
    fused_stage1_kernel<<<G1_BLOCKS + POOL_BLOCKS, 128>>>(dense, d_w1, d_b1, H1,
                                                          sidx, emb, FEAT);

    // 2) dense MLP layer 2: H1 @ [64,512]^T -> FEAT columns [0,64) (relu)
    {
        dim3 grid(EMB_DIM/32, BATCH/32);              // 2 x 128 = 256 blocks, 64 thr
        gemm_kernel<32,32,16,4,4><<<grid, 64>>>(H1, d_w2, d_b2, FEAT,
                                                DENSE_DIM, FEAT_DIM);
    }
    // 3) output MLP layer 1: FEAT[4096,1728] @ [512,1728]^T -> H2 (relu)
    {
        dim3 grid(HIDDEN_OUT/64, BATCH/128);          // 8 x 32 = 256 blocks, 128 thr
        gemm_kernel<128,64,16,8,8><<<grid, 128>>>(FEAT, o_w1, o_b1, H2,
                                                  FEAT_DIM, HIDDEN_OUT);
    }
    // 4) output MLP layer 2: dot + relu -> out
    out_final_kernel<<<(BATCH*32)/256, 256>>>(H2, o_w2, o_b2, out);
}

// round 10
// speedup vs baseline: 1.9867x; 1.9867x over previous
#include <cuda_runtime.h>
#include <cuda_bf16.h>
#include <cstdint>

// Problem constants (match reference)
#define NUM_TABLES 26
#define NUM_EMB    100000
#define EMB_DIM    64
#define DENSE_DIM  512
#define BATCH      4096
#define BAG        50
#define HIDDEN_OUT 512
#define FEAT_DIM   (NUM_TABLES * EMB_DIM + EMB_DIM)   // 1728

// Scratch (device globals — no allocation allowed)
__device__ __align__(256) float g_H1[BATCH * DENSE_DIM];
__device__ __align__(256) float g_FEAT[BATCH * FEAT_DIM];
__device__ __align__(256) float g_H2[BATCH * HIDDEN_OUT];
__device__ int g_idx_is64;

// ---------------------------------------------------------------------------
// TF32 helpers
// ---------------------------------------------------------------------------
__device__ __forceinline__ uint32_t f2tf32(float f)
{
    uint32_t r;
    asm("cvt.rna.tf32.f32 %0, %1;" : "=r"(r) : "f"(f));
    return r;
}
__device__ __forceinline__ void mma_tf32(float c[4],
                                         const uint32_t a[4],
                                         const uint32_t b[2])
{
    asm("mma.sync.aligned.m16n8k8.row.col.f32.tf32.tf32.f32 "
        "{%0,%1,%2,%3}, {%4,%5,%6,%7}, {%8,%9}, {%0,%1,%2,%3};"
        : "+f"(c[0]), "+f"(c[1]), "+f"(c[2]), "+f"(c[3])
        : "r"(a[0]), "r"(a[1]), "r"(a[2]), "r"(a[3]), "r"(b[0]), "r"(b[1]));
}

// ---------------------------------------------------------------------------
// Index dtype detection (int64 LE buffer has all-zero odd words).
// ---------------------------------------------------------------------------
__global__ void detect_idx_dtype_kernel(const int* __restrict__ idx)
{
    int o = 0;
    #pragma unroll 8
    for (int i = 1; i < 512; i += 2) o |= idx[i];
    g_idx_is64 = (o == 0) ? 1 : 0;
}

// ---------------------------------------------------------------------------
// TF32 tensor-core GEMM body: C = relu(A @ B^T + bias)
// A [M,K] row-major, B [N,K] row-major (== .col operand of mma directly).
// Block 64x64, 128 threads (4 warps, each 32x32 = 2 m-frags x 4 n-frags).
// smem tiles [64][36] (pad 4) -> all fragment LDS bank-conflict-free:
// bank = (36*quad + tq) % 32 = 4*quad + tq, distinct over the warp.
// Requires K % 32 == 0, M % 64 == 0, N % 64 == 0.
// ---------------------------------------------------------------------------
#define TF_LDS 36   // 32 + 4 pad (keeps 16B alignment: 36*4B = 144B = 9*16B)

__device__ __forceinline__
void gemm_tf32_body(const float* __restrict__ A,
                    const float* __restrict__ B,
                    const float* __restrict__ bias,
                    float* __restrict__ C,
                    int K, int ldc, int bm0, int bn0,
                    uint32_t* __restrict__ As,    // [64][TF_LDS]
                    uint32_t* __restrict__ Bs)    // [64][TF_LDS]
{
    const int tid  = threadIdx.x;
    const int lane = tid & 31;
    const int w    = tid >> 5;
    const int quad = lane >> 2;
    const int tq   = lane & 3;
    const int wm   = (w & 1) * 32;
    const int wn   = (w >> 1) * 32;

    float acc[2][4][4];
    #pragma unroll
    for (int mi = 0; mi < 2; mi++)
        #pragma unroll
        for (int nj = 0; nj < 4; nj++)
            #pragma unroll
            for (int c = 0; c < 4; c++) acc[mi][nj][c] = 0.f;

    for (int k0 = 0; k0 < K; k0 += 32) {
        // Load + convert tiles. Each instruction: 4 warps x 4 rows of 128B,
        // perfectly coalesced (flat = r*512 + tid*4 -> row = flat/32).
        #pragma unroll
        for (int r = 0; r < 4; r++) {
            int flat = r * 512 + tid * 4;
            int row  = flat >> 5;
            int kk   = flat & 31;
            float4 va = *(const float4*)(A + (size_t)(bm0 + row) * K + k0 + kk);
            uint4 ta = make_uint4(f2tf32(va.x), f2tf32(va.y),
                                  f2tf32(va.z), f2tf32(va.w));
            *(uint4*)&As[row * TF_LDS + kk] = ta;
            float4 vb = *(const float4*)(B + (size_t)(bn0 + row) * K + k0 + kk);
            uint4 tb = make_uint4(f2tf32(vb.x), f2tf32(vb.y),
                                  f2tf32(vb.z), f2tf32(vb.w));
            *(uint4*)&Bs[row * TF_LDS + kk] = tb;
        }
        __syncthreads();

        #pragma unroll
        for (int kc = 0; kc < 32; kc += 8) {
            uint32_t af[2][4], bf[4][2];
            #pragma unroll
            for (int mi = 0; mi < 2; mi++) {
                int r0 = wm + mi * 16 + quad;
                af[mi][0] = As[(r0    ) * TF_LDS + kc + tq];
                af[mi][1] = As[(r0 + 8) * TF_LDS + kc + tq];
                af[mi][2] = As[(r0    ) * TF_LDS + kc + tq + 4];
                af[mi][3] = As[(r0 + 8) * TF_LDS + kc + tq + 4];
            }
            #pragma unroll
            for (int nj = 0; nj < 4; nj++) {
                int n = wn + nj * 8 + quad;
                bf[nj][0] = Bs[n * TF_LDS + kc + tq];
                bf[nj][1] = Bs[n * TF_LDS + kc + tq + 4];
            }
            #pragma unroll
            for (int mi = 0; mi < 2; mi++)
                #pragma unroll
                for (int nj = 0; nj < 4; nj++)
                    mma_tf32(acc[mi][nj], af[mi], bf[nj]);
        }
        __syncthreads();
    }

    // Epilogue: bias + relu. (c0,c1) and (c2,c3) are contiguous column pairs.
    #pragma unroll
    for (int mi = 0; mi < 2; mi++) {
        int row0 = bm0 + wm + mi * 16 + quad;
        #pragma unroll
        for (int nj = 0; nj < 4; nj++) {
            int col = bn0 + wn + nj * 8 + 2 * tq;
            float2 bv = *(const float2*)(bias + col);
            float2 o0, o1;
            o0.x = fmaxf(acc[mi][nj][0] + bv.x, 0.f);
            o0.y = fmaxf(acc[mi][nj][1] + bv.y, 0.f);
            o1.x = fmaxf(acc[mi][nj][2] + bv.x, 0.f);
            o1.y = fmaxf(acc[mi][nj][3] + bv.y, 0.f);
            *(float2*)(C + (size_t)(row0    ) * ldc + col) = o0;
            *(float2*)(C + (size_t)(row0 + 8) * ldc + col) = o1;
        }
    }
}

// ---------------------------------------------------------------------------
// Scalar GEMM body (R8-proven) — used only for the small gemm2.
// ---------------------------------------------------------------------------
template<int BM, int BN, int BK, int TM, int TN, int THREADS>
__device__ __forceinline__
void gemm_body(const float* __restrict__ A, const float* __restrict__ B,
               const float* __restrict__ bias, float* __restrict__ C,
               int K, int ldc, int bm0, int bn0,
               float* __restrict__ As_, float* __restrict__ Bs_)
{
    const int tid = threadIdx.x;
    const int tx  = tid % (BN/TN);
    const int ty  = tid / (BN/TN);
    float (*As)[BM] = (float(*)[BM])As_;
    float (*Bs)[BN] = (float(*)[BN])Bs_;

    float acc[TM][TN];
    #pragma unroll
    for (int i = 0; i < TM; i++)
        #pragma unroll
        for (int j = 0; j < TN; j++) acc[i][j] = 0.f;

    for (int k0 = 0; k0 < K; k0 += BK) {
        #pragma unroll
        for (int i = tid; i < BM*BK/4; i += THREADS) {
            int row = (i*4) / BK, kk = (i*4) % BK;
            float4 v = *(const float4*)(A + (size_t)(bm0 + row) * K + k0 + kk);
            As[kk+0][row] = v.x; As[kk+1][row] = v.y;
            As[kk+2][row] = v.z; As[kk+3][row] = v.w;
        }
        #pragma unroll
        for (int i = tid; i < BN*BK/4; i += THREADS) {
            int row = (i*4) / BK, kk = (i*4) % BK;
            float4 v = *(const float4*)(B + (size_t)(bn0 + row) * K + k0 + kk);
            Bs[kk+0][row] = v.x; Bs[kk+1][row] = v.y;
            Bs[kk+2][row] = v.z; Bs[kk+3][row] = v.w;
        }
        __syncthreads();
        #pragma unroll
        for (int k = 0; k < BK; k++) {
            float a[TM], b[TN];
            #pragma unroll
            for (int i = 0; i < TM; i++) a[i] = As[k][ty*TM + i];
            #pragma unroll
            for (int j = 0; j < TN; j += 4) {
                float4 v = *(const float4*)&Bs[k][tx*TN + j];
                b[j+0] = v.x; b[j+1] = v.y; b[j+2] = v.z; b[j+3] = v.w;
            }
            #pragma unroll
            for (int i = 0; i < TM; i++)
                #pragma unroll
                for (int j = 0; j < TN; j++)
                    acc[i][j] = fmaf(a[i], b[j], acc[i][j]);
        }
        __syncthreads();
    }
    #pragma unroll
    for (int i = 0; i < TM; i++) {
        int row = bm0 + ty*TM + i;
        int col = bn0 + tx*TN;
        float4 o;
        o.x = fmaxf(acc[i][0] + bias[col+0], 0.f);
        o.y = fmaxf(acc[i][1] + bias[col+1], 0.f);
        o.z = fmaxf(acc[i][2] + bias[col+2], 0.f);
        o.w = fmaxf(acc[i][3] + bias[col+3], 0.f);
        *(float4*)(C + (size_t)row * ldc + col) = o;
    }
}

// ---------------------------------------------------------------------------
// Pool body (proven): one warp per bag, runtime int32/int64, clamped indices.
// ---------------------------------------------------------------------------
__device__ __forceinline__
void pool_body(int bag, const int* __restrict__ idx,
               const float* __restrict__ tables, float* __restrict__ feat)
{
    if (bag >= NUM_TABLES * BATCH) return;
    const int t    = bag / BATCH;
    const int b    = bag % BATCH;
    const int lane = threadIdx.x & 31;
    const int is64 = g_idx_is64;

    const size_t bag_off = ((size_t)t * BATCH + b) * BAG;
    const float* tbl = tables + (size_t)t * NUM_EMB * EMB_DIM;

    float2 acc = make_float2(0.f, 0.f);
    #pragma unroll
    for (int l0 = 0; l0 < BAG; l0 += 10) {
        int ids[10];
        if (is64) {
            const long long* ip = (const long long*)idx + bag_off + l0;
            #pragma unroll
            for (int j = 0; j < 10; j++) ids[j] = (int)__ldg(&ip[j]);
        } else {
            const int* ip = idx + bag_off + l0;
            #pragma unroll
            for (int j = 0; j < 10; j++) ids[j] = __ldg(&ip[j]);
        }
        #pragma unroll
        for (int j = 0; j < 10; j++) {
            int id = min(max(ids[j], 0), NUM_EMB - 1);
            const float2* row = (const float2*)(tbl + (size_t)id * EMB_DIM);
            float2 v = __ldg(&row[lane]);
            acc.x += v.x; acc.y += v.y;
        }
    }
    float* out = feat + (size_t)b * FEAT_DIM + EMB_DIM + (size_t)t * EMB_DIM;
    ((float2*)out)[lane] = acc;
}

// ---------------------------------------------------------------------------
// Stage 1 fused (128 thr): blocks [0,512) = tf32 gemm1 tiles (64x64),
// rest = pooling (4 warps/block).
// ---------------------------------------------------------------------------
#define G1_NB (DENSE_DIM / 64)                         // 8
#define G1_BLOCKS (G1_NB * (BATCH / 64))               // 512
#define POOL_WPB 4
#define POOL_BLOCKS ((NUM_TABLES * BATCH) / POOL_WPB)  // 26624

__global__ __launch_bounds__(128)
void fused_stage1_kernel(const float* __restrict__ dense,
                         const float* __restrict__ w1,
                         const float* __restrict__ b1,
                         float* __restrict__ H1,
                         const int* __restrict__ sidx,
                         const float* __restrict__ emb,
                         float* __restrict__ feat)
{
    __shared__ __align__(16) uint32_t smem[2 * 64 * TF_LDS];   // 18 KB
    if (blockIdx.x < G1_BLOCKS) {
        int bn = blockIdx.x % G1_NB;
        int bm = blockIdx.x / G1_NB;
        gemm_tf32_body(dense, w1, b1, H1, DENSE_DIM, DENSE_DIM,
                       bm * 64, bn * 64, smem, smem + 64 * TF_LDS);
    } else {
        int bag = (blockIdx.x - G1_BLOCKS) * POOL_WPB + (threadIdx.x >> 5);
        pool_body(bag, sidx, emb, feat);
    }
}

// ---------------------------------------------------------------------------
// Standalone tf32 GEMM kernel (gemm4)
// ---------------------------------------------------------------------------
__global__ __launch_bounds__(128)
void gemm_tf32_kernel(const float* __restrict__ A, const float* __restrict__ B,
                      const float* __restrict__ bias, float* __restrict__ C,
                      int K, int ldc)
{
    __shared__ __align__(16) uint32_t smem[2 * 64 * TF_LDS];
    gemm_tf32_body(A, B, bias, C, K, ldc,
                   blockIdx.y * 64, blockIdx.x * 64,
                   smem, smem + 64 * TF_LDS);
}

// ---------------------------------------------------------------------------
// Scalar GEMM kernel (gemm2, R8 config)
// ---------------------------------------------------------------------------
template<int BM, int BN, int BK, int TM, int TN>
__global__ __launch_bounds__((BM/TM)*(BN/TN))
void gemm_kernel(const float* __restrict__ A, const float* __restrict__ B,
                 const float* __restrict__ bias, float* __restrict__ C,
                 int K, int ldc)
{
    constexpr int THREADS = (BM/TM)*(BN/TN);
    __shared__ __align__(16) float smem[BK*BM + BK*BN];
    gemm_body<BM, BN, BK, TM, TN, THREADS>(A, B, bias, C, K, ldc,
                                           blockIdx.y * BM, blockIdx.x * BN,
                                           smem, smem + BK * BM);
}

// ---------------------------------------------------------------------------
// Final layer: logits[b] = relu( dot(H2[b,:], w2) + b2 ). One warp per row.
// ---------------------------------------------------------------------------
__global__ __launch_bounds__(256)
void out_final_kernel(const float* __restrict__ H2,
                      const float* __restrict__ w2,
                      const float* __restrict__ b2,
                      float* __restrict__ out)
{
    const int warp = (blockIdx.x * blockDim.x + threadIdx.x) >> 5;
    const int lane = threadIdx.x & 31;
    if (warp >= BATCH) return;

    const float4* h4 = (const float4*)(H2 + (size_t)warp * HIDDEN_OUT);
    const float4* w4 = (const float4*)w2;
    float s = 0.f;
    #pragma unroll
    for (int i = 0; i < HIDDEN_OUT/4/32; i++) {
        float4 h = h4[lane + i*32];
        float4 w = __ldg(&w4[lane + i*32]);
        s = fmaf(h.x, w.x, s); s = fmaf(h.y, w.y, s);
        s = fmaf(h.z, w.z, s); s = fmaf(h.w, w.w, s);
    }
    #pragma unroll
    for (int o = 16; o; o >>= 1) s += __shfl_xor_sync(0xFFFFFFFFu, s, o);
    if (lane == 0) out[warp] = fmaxf(s + b2[0], 0.f);
}

// ---------------------------------------------------------------------------
// Launch
// ---------------------------------------------------------------------------
extern "C" void kernel_launch(void* const* d_in, const int* in_sizes, int n_in,
                              void* d_out, int out_size)
{
    const float* dense = (const float*)d_in[0];       // [4096, 512]
    const int*   sidx  = (const int*)d_in[1];         // [26, 4096, 50]
    const float* emb   = (const float*)d_in[2];       // [26, 100000, 64]
    const float* d_w1  = (const float*)d_in[3];       // [512, 512]
    const float* d_b1  = (const float*)d_in[4];       // [512]
    const float* d_w2  = (const float*)d_in[5];       // [64, 512]
    const float* d_b2  = (const float*)d_in[6];       // [64]
    const float* o_w1  = (const float*)d_in[7];       // [512, 1728]
    const float* o_b1  = (const float*)d_in[8];       // [512]
    const float* o_w2  = (const float*)d_in[9];       // [1, 512]
    const float* o_b2  = (const float*)d_in[10];      // [1]
    float* out = (float*)d_out;                       // [4096, 1]

    static float* H1   = nullptr;
    static float* FEAT = nullptr;
    static float* H2   = nullptr;
    if (!H1) {
        cudaGetSymbolAddress((void**)&H1,   g_H1);
        cudaGetSymbolAddress((void**)&FEAT, g_FEAT);
        cudaGetSymbolAddress((void**)&H2,   g_H2);
    }

    // 0) index dtype detection
    detect_idx_dtype_kernel<<<1, 1>>>(sidx);

    // 1) fused: tf32 gemm1 (dense MLP layer 1 -> H1) + pooling -> FEAT
    fused_stage1_kernel<<<G1_BLOCKS + POOL_BLOCKS, 128>>>(dense, d_w1, d_b1, H1,
                                                          sidx, emb, FEAT);

    // 2) dense MLP layer 2 (scalar, small): H1 @ [64,512]^T -> FEAT[:, 0:64)
    {
        dim3 grid(EMB_DIM/32, BATCH/32);              // 2 x 128 = 256 blocks
        gemm_kernel<32,32,16,2,4><<<grid, 128>>>(H1, d_w2, d_b2, FEAT,
                                                 DENSE_DIM, FEAT_DIM);
    }
    // 3) output MLP layer 1 (tf32): FEAT @ [512,1728]^T -> H2
    {
        dim3 grid(HIDDEN_OUT/64, BATCH/64);           // 8 x 64 = 512 blocks
        gemm_tf32_kernel<<<grid, 128>>>(FEAT, o_w1, o_b1, H2,
                                        FEAT_DIM, HIDDEN_OUT);
    }
    // 4) output MLP layer 2: dot + relu -> out
    out_final_kernel<<<(BATCH*32)/256, 256>>>(H2, o_w2, o_b2, out);
}